// round 6
// baseline (speedup 1.0000x reference)
#include <cuda_runtime.h>
#include <stdint.h>

// Quantum 2x2 gate apply on qubit axis TARGET=5 of state (2,)^24 x (4,) f32.
// Converged shape: one float4-pair per thread, fully coalesced, flat grid.
// HBM-bound at the mixed read/write ceiling (~82% DRAM, ~6.5 TB/s).
// Polish: pauli loaded as a single float4 (one LDG.128), block=512.

static constexpr uint32_t SHIFT  = 18u;            // target stride in float4 units
static constexpr uint32_t NPAIRS = 1u << 23;       // 8,388,608 pairs
static constexpr int THREADS = 512;

__global__ __launch_bounds__(THREADS)
void gate_apply_kernel(const float4* __restrict__ state,
                       const float4* __restrict__ pauli4,
                       float4* __restrict__ out)
{
    uint32_t v = blockIdx.x * blockDim.x + threadIdx.x;   // grid exactly covers NPAIRS

    const float4 p = __ldg(pauli4);   // p.x=p00 p.y=p01 p.z=p10 p.w=p11

    uint32_t low  = v & ((1u << SHIFT) - 1u);
    uint32_t idx0 = ((v >> SHIFT) << (SHIFT + 1u)) | low;  // target bit = 0
    uint32_t idx1 = idx0 + (1u << SHIFT);                  // target bit = 1

    float4 s0 = state[idx0];
    float4 s1 = state[idx1];

    float4 o0, o1;
    o0.x = p.x * s0.x + p.y * s1.x;
    o0.y = p.x * s0.y + p.y * s1.y;
    o0.z = p.x * s0.z + p.y * s1.z;
    o0.w = p.x * s0.w + p.y * s1.w;

    o1.x = p.z * s0.x + p.w * s1.x;
    o1.y = p.z * s0.y + p.w * s1.y;
    o1.z = p.z * s0.z + p.w * s1.z;
    o1.w = p.z * s0.w + p.w * s1.w;

    out[idx0] = o0;
    out[idx1] = o1;
}

extern "C" void kernel_launch(void* const* d_in, const int* in_sizes, int n_in,
                              void* d_out, int out_size)
{
    const float4* state  = (const float4*)d_in[0];
    const float4* pauli4 = (const float4*)d_in[1];
    float4* out = (float4*)d_out;

    const unsigned blocks = NPAIRS / THREADS;   // 16384, exact cover
    gate_apply_kernel<<<blocks, THREADS>>>(state, pauli4, out);
}

// round 7
// speedup vs baseline: 1.0016x; 1.0016x over previous
#include <cuda_runtime.h>
#include <stdint.h>

// Quantum 2x2 gate apply on qubit axis TARGET=5 of state (2,)^24 x (4,) f32.
// FINAL (converged): one float4-pair per thread, fully coalesced, flat grid,
// 32-bit index math, block=256. HBM-bound at the mixed read/write ceiling
// (~82% DRAM, ~6.5 TB/s realized). Measured best of 6 shape variants:
//   f4-pair (this): 73.9us ncu / 82.0us bench, DRAM 82.3%
//   f4 x2 MLP4:     75.0us, v8 256-bit: 74.0us, persistent: 78.5us,
//   f4-pauli/512:   80.2us  -- all neutral or worse.

static constexpr uint32_t SHIFT  = 18u;            // target stride in float4 units
static constexpr uint32_t NPAIRS = 1u << 23;       // 8,388,608 pairs

__global__ __launch_bounds__(256)
void gate_apply_kernel(const float4* __restrict__ state,
                       const float*  __restrict__ pauli,
                       float4* __restrict__ out)
{
    uint32_t v = blockIdx.x * blockDim.x + threadIdx.x;   // grid exactly covers NPAIRS

    const float p00 = pauli[0];
    const float p01 = pauli[1];
    const float p10 = pauli[2];
    const float p11 = pauli[3];

    uint32_t low  = v & ((1u << SHIFT) - 1u);
    uint32_t idx0 = ((v >> SHIFT) << (SHIFT + 1u)) | low;  // target bit = 0
    uint32_t idx1 = idx0 + (1u << SHIFT);                  // target bit = 1

    float4 s0 = state[idx0];
    float4 s1 = state[idx1];

    float4 o0, o1;
    o0.x = p00 * s0.x + p01 * s1.x;
    o0.y = p00 * s0.y + p01 * s1.y;
    o0.z = p00 * s0.z + p01 * s1.z;
    o0.w = p00 * s0.w + p01 * s1.w;

    o1.x = p10 * s0.x + p11 * s1.x;
    o1.y = p10 * s0.y + p11 * s1.y;
    o1.z = p10 * s0.z + p11 * s1.z;
    o1.w = p10 * s0.w + p11 * s1.w;

    out[idx0] = o0;
    out[idx1] = o1;
}

extern "C" void kernel_launch(void* const* d_in, const int* in_sizes, int n_in,
                              void* d_out, int out_size)
{
    const float4* state = (const float4*)d_in[0];
    const float*  pauli = (const float*)d_in[1];
    float4* out = (float4*)d_out;

    const int threads = 256;
    const unsigned blocks = NPAIRS / threads;   // 32768, exact cover
    gate_apply_kernel<<<blocks, threads>>>(state, pauli, out);
}

// round 8
// speedup vs baseline: 1.0047x; 1.0031x over previous
#include <cuda_runtime.h>
#include <stdint.h>

// Quantum 2x2 gate apply on qubit axis TARGET=5 of state (2,)^24 x (4,) f32.
// Converged shape (R5/R7): one float4-pair per thread, fully coalesced,
// flat grid, block=256, 32-bit index math. DRAM-bound at ~82% / 6.5 TB/s.
// R8 variant: stores use streaming eviction (.cs) so the 256MB write stream
// does not displace read sectors in L2; loads keep default caching.

static constexpr uint32_t SHIFT  = 18u;            // target stride in float4 units
static constexpr uint32_t NPAIRS = 1u << 23;       // 8,388,608 pairs

__device__ __forceinline__ void stcs4(float4* p, float4 v) {
    asm volatile("st.global.cs.v4.f32 [%0], {%1,%2,%3,%4};"
                 :: "l"(p), "f"(v.x), "f"(v.y), "f"(v.z), "f"(v.w));
}

__global__ __launch_bounds__(256)
void gate_apply_kernel(const float4* __restrict__ state,
                       const float*  __restrict__ pauli,
                       float4* __restrict__ out)
{
    uint32_t v = blockIdx.x * blockDim.x + threadIdx.x;   // grid exactly covers NPAIRS

    const float p00 = pauli[0];
    const float p01 = pauli[1];
    const float p10 = pauli[2];
    const float p11 = pauli[3];

    uint32_t low  = v & ((1u << SHIFT) - 1u);
    uint32_t idx0 = ((v >> SHIFT) << (SHIFT + 1u)) | low;  // target bit = 0
    uint32_t idx1 = idx0 + (1u << SHIFT);                  // target bit = 1

    float4 s0 = state[idx0];
    float4 s1 = state[idx1];

    float4 o0, o1;
    o0.x = p00 * s0.x + p01 * s1.x;
    o0.y = p00 * s0.y + p01 * s1.y;
    o0.z = p00 * s0.z + p01 * s1.z;
    o0.w = p00 * s0.w + p01 * s1.w;

    o1.x = p10 * s0.x + p11 * s1.x;
    o1.y = p10 * s0.y + p11 * s1.y;
    o1.z = p10 * s0.z + p11 * s1.z;
    o1.w = p10 * s0.w + p11 * s1.w;

    stcs4(out + idx0, o0);
    stcs4(out + idx1, o1);
}

extern "C" void kernel_launch(void* const* d_in, const int* in_sizes, int n_in,
                              void* d_out, int out_size)
{
    const float4* state = (const float4*)d_in[0];
    const float*  pauli = (const float*)d_in[1];
    float4* out = (float4*)d_out;

    const int threads = 256;
    const unsigned blocks = NPAIRS / threads;   // 32768, exact cover
    gate_apply_kernel<<<blocks, threads>>>(state, pauli, out);
}

// round 9
// speedup vs baseline: 1.0078x; 1.0031x over previous
#include <cuda_runtime.h>
#include <stdint.h>

// Quantum 2x2 gate apply on qubit axis TARGET=5 of state (2,)^24 x (4,) f32.
// FINAL (converged, R5/R7 measured optimum): one float4-pair per thread,
// fully coalesced flat grid, block=256, 32-bit index math, default caching.
// DRAM-bound at the HBM3e mixed read/write ceiling: 82.3% DRAM, 6.5 TB/s,
// ~74us kernel / ~82us bench. Falsified alternatives: MLP4 front-batch,
// v8 256-bit, persistent grid-stride, vectorized pauli load, block 512,
// .cs on loads, .cs on stores — all neutral or worse.

static constexpr uint32_t SHIFT  = 18u;            // target stride in float4 units
static constexpr uint32_t NPAIRS = 1u << 23;       // 8,388,608 pairs

__global__ __launch_bounds__(256)
void gate_apply_kernel(const float4* __restrict__ state,
                       const float*  __restrict__ pauli,
                       float4* __restrict__ out)
{
    uint32_t v = blockIdx.x * blockDim.x + threadIdx.x;   // grid exactly covers NPAIRS

    const float p00 = pauli[0];
    const float p01 = pauli[1];
    const float p10 = pauli[2];
    const float p11 = pauli[3];

    uint32_t low  = v & ((1u << SHIFT) - 1u);
    uint32_t idx0 = ((v >> SHIFT) << (SHIFT + 1u)) | low;  // target bit = 0
    uint32_t idx1 = idx0 + (1u << SHIFT);                  // target bit = 1

    float4 s0 = state[idx0];
    float4 s1 = state[idx1];

    float4 o0, o1;
    o0.x = p00 * s0.x + p01 * s1.x;
    o0.y = p00 * s0.y + p01 * s1.y;
    o0.z = p00 * s0.z + p01 * s1.z;
    o0.w = p00 * s0.w + p01 * s1.w;

    o1.x = p10 * s0.x + p11 * s1.x;
    o1.y = p10 * s0.y + p11 * s1.y;
    o1.z = p10 * s0.z + p11 * s1.z;
    o1.w = p10 * s0.w + p11 * s1.w;

    out[idx0] = o0;
    out[idx1] = o1;
}

extern "C" void kernel_launch(void* const* d_in, const int* in_sizes, int n_in,
                              void* d_out, int out_size)
{
    const float4* state = (const float4*)d_in[0];
    const float*  pauli = (const float*)d_in[1];
    float4* out = (float4*)d_out;

    const int threads = 256;
    const unsigned blocks = NPAIRS / threads;   // 32768, exact cover
    gate_apply_kernel<<<blocks, threads>>>(state, pauli, out);
}